// round 1
// baseline (speedup 1.0000x reference)
#include <cuda_runtime.h>
#include <math.h>

// Problem constants
#define HIN 256
#define WIN 256
#define HOUT 128
#define WOUT 128
#define CIN 128
#define CO_OFF 1152      // G*2*K = 64*2*9
#define CO_MSK 576       // G*K
#define CO_TOTAL 1728
#define CO_TILE 16
#define CK 16            // input channels per shared-weight chunk
#define GRP 64
#define NPIX (HOUT*WOUT) // 16384

// Scratch (allocation-guard-safe __device__ globals)
__device__ float g_offset[(size_t)2 * CO_OFF * NPIX];   // [B][1152][128][128]
__device__ float g_mask  [(size_t)2 * CO_MSK * NPIX];   // [B][576][128][128]

// ---------------------------------------------------------------------------
// Conv kernel: computes offset conv (co < 1152) and mask conv (co >= 1152,
// with fused sigmoid). Block = 16 out-channels x (16x16) output pixel tile.
// Weights staged in shared as [cc*9+tap][16 co] so inner loop is
// 1 LDG + 4 broadcast LDS.128 + 16 FFMA.
// ---------------------------------------------------------------------------
__global__ __launch_bounds__(256) void conv_offmask_kernel(
    const float* __restrict__ x,
    const float* __restrict__ w_off, const float* __restrict__ b_off,
    const float* __restrict__ w_msk, const float* __restrict__ b_msk)
{
    __shared__ float w_sh[CK * 9 * CO_TILE];   // 9216 B

    const int b    = blockIdx.z;
    const int co0  = blockIdx.y * CO_TILE;
    const int tile = blockIdx.x;               // 0..63 (8x8 tiles of 16x16)
    const int tx = threadIdx.x & 15;
    const int ty = threadIdx.x >> 4;
    const int ho = (tile >> 3) * 16 + ty;
    const int wo = (tile & 7)  * 16 + tx;
    const int hi0 = ho * 2 - 1;
    const int wi0 = wo * 2 - 1;

    const bool is_mask = (co0 >= CO_OFF);
    const float* wg = is_mask ? (w_msk + (size_t)(co0 - CO_OFF) * (CIN * 9))
                              : (w_off + (size_t)co0 * (CIN * 9));

    float acc[CO_TILE];
#pragma unroll
    for (int i = 0; i < CO_TILE; i++) acc[i] = 0.f;

    const float* xb = x + (size_t)b * CIN * HIN * WIN;

    for (int cb = 0; cb < CIN; cb += CK) {
        __syncthreads();
        // load weights for this channel chunk: shared[(cc*9+tap)*16 + co_l]
        for (int i = threadIdx.x; i < CK * 9 * CO_TILE; i += 256) {
            int co_l = i & 15;
            int r    = i >> 4;                     // cc*9 + tap
            w_sh[r * CO_TILE + co_l] = wg[(size_t)co_l * (CIN * 9) + cb * 9 + r];
        }
        __syncthreads();

#pragma unroll 1
        for (int cc = 0; cc < CK; ++cc) {
            const float* xc = xb + (size_t)(cb + cc) * (HIN * WIN);
            const float* wrow = &w_sh[cc * 9 * CO_TILE];
#pragma unroll
            for (int tap = 0; tap < 9; ++tap) {
                const int ki = tap / 3, kj = tap % 3;
                const int hi = hi0 + ki;
                const int wi = wi0 + kj;
                float xv = 0.f;
                if ((unsigned)hi < HIN && (unsigned)wi < WIN)
                    xv = __ldg(xc + hi * WIN + wi);
                const float4* wv = (const float4*)(wrow + tap * CO_TILE);
                float4 a0 = wv[0], a1 = wv[1], a2 = wv[2], a3 = wv[3];
                acc[0]  += xv * a0.x;  acc[1]  += xv * a0.y;
                acc[2]  += xv * a0.z;  acc[3]  += xv * a0.w;
                acc[4]  += xv * a1.x;  acc[5]  += xv * a1.y;
                acc[6]  += xv * a1.z;  acc[7]  += xv * a1.w;
                acc[8]  += xv * a2.x;  acc[9]  += xv * a2.y;
                acc[10] += xv * a2.z;  acc[11] += xv * a2.w;
                acc[12] += xv * a3.x;  acc[13] += xv * a3.y;
                acc[14] += xv * a3.z;  acc[15] += xv * a3.w;
            }
        }
    }

    const int pix = ho * WOUT + wo;
    if (!is_mask) {
#pragma unroll
        for (int i = 0; i < CO_TILE; i++) {
            float v = acc[i] + __ldg(b_off + co0 + i);
            g_offset[((size_t)b * CO_OFF + co0 + i) * NPIX + pix] = v;
        }
    } else {
        const int cm0 = co0 - CO_OFF;
#pragma unroll
        for (int i = 0; i < CO_TILE; i++) {
            float v = acc[i] + __ldg(b_msk + cm0 + i);
            g_mask[((size_t)b * CO_MSK + cm0 + i) * NPIX + pix] = 1.f / (1.f + expf(-v));
        }
    }
}

// ---------------------------------------------------------------------------
// Deformable sampling + grouped 1-group conv core.
// One thread per (b, g, output pixel). Cg = 2 input channels, 2 out channels.
// ---------------------------------------------------------------------------
__global__ __launch_bounds__(128) void deform_kernel(
    const float* __restrict__ x,
    const float* __restrict__ w_deform,
    float* __restrict__ out)
{
    __shared__ float wsh[36];  // [o=2][c=2][k=9]
    const int b = blockIdx.z;
    const int g = blockIdx.y;
    const int pix = blockIdx.x * 128 + threadIdx.x;

    if (threadIdx.x < 36)
        wsh[threadIdx.x] = w_deform[g * 36 + threadIdx.x];
    __syncthreads();

    const int ho = pix >> 7;       // WOUT = 128
    const int wo = pix & 127;

    const float* offp = g_offset + ((size_t)(b * GRP + g) * 18) * NPIX + pix;
    const float* mp   = g_mask   + ((size_t)(b * GRP + g) * 9)  * NPIX + pix;
    const float* xc0  = x + (size_t)(b * CIN + g * 2) * (HIN * WIN);
    const float* xc1  = xc0 + HIN * WIN;

    float acc0 = 0.f, acc1 = 0.f;

#pragma unroll
    for (int k = 0; k < 9; k++) {
        const float dy = offp[(2 * k)     * NPIX];
        const float dx = offp[(2 * k + 1) * NPIX];
        const float m  = mp[k * NPIX];

        const float py = dy + (float)(2 * ho - 1 + k / 3);
        const float px = dx + (float)(2 * wo - 1 + k % 3);
        const float yf = floorf(py);
        const float xf = floorf(px);
        const int y0 = (int)yf;
        const int x0 = (int)xf;
        const float wy = py - yf;
        const float wx = px - xf;

        float v0 = 0.f, v1 = 0.f;
#pragma unroll
        for (int c2 = 0; c2 < 4; c2++) {
            const int yy = y0 + (c2 >> 1);
            const int xx = x0 + (c2 & 1);
            const float wt = ((c2 >> 1) ? wy : (1.f - wy)) *
                             ((c2 & 1)  ? wx : (1.f - wx));
            if (yy >= 0 && yy < HIN && xx >= 0 && xx < WIN) {
                const int idx = yy * WIN + xx;
                v0 += wt * __ldg(xc0 + idx);
                v1 += wt * __ldg(xc1 + idx);
            }
        }
        v0 *= m;
        v1 *= m;
        acc0 += wsh[k]      * v0 + wsh[9 + k]  * v1;
        acc1 += wsh[18 + k] * v0 + wsh[27 + k] * v1;
    }

    out[((size_t)(b * CIN + g * 2))     * NPIX + pix] = acc0;
    out[((size_t)(b * CIN + g * 2) + 1) * NPIX + pix] = acc1;
}

// ---------------------------------------------------------------------------
// Launch
// ---------------------------------------------------------------------------
extern "C" void kernel_launch(void* const* d_in, const int* in_sizes, int n_in,
                              void* d_out, int out_size)
{
    const float* x        = (const float*)d_in[0];
    const float* w_offset = (const float*)d_in[1];
    const float* b_offset = (const float*)d_in[2];
    const float* w_mask   = (const float*)d_in[3];
    const float* b_mask   = (const float*)d_in[4];
    const float* w_deform = (const float*)d_in[5];
    float* out = (float*)d_out;

    {
        dim3 grid(64, CO_TOTAL / CO_TILE, 2);   // (pixel tiles, 108 co-groups, B)
        conv_offmask_kernel<<<grid, 256>>>(x, w_offset, b_offset, w_mask, b_mask);
    }
    {
        dim3 grid(NPIX / 128, GRP, 2);          // (pixel chunks, groups, B)
        deform_kernel<<<grid, 128>>>(x, w_deform, out);
    }
}

// round 5
// speedup vs baseline: 3.5391x; 3.5391x over previous
#include <cuda_runtime.h>
#include <cstdint>
#include <math.h>

// ---------------- problem constants ----------------
#define HIN 256
#define WIN 256
#define HOUT 128
#define WOUT 128
#define CIN 128
#define CO_OFF 1152      // G*2*K
#define CO_MSK 576       // G*K
#define CO_TOT 1728
#define MPAD 1792        // 14 * 128
#define KTOT 1152        // CIN * 9
#define NPIX 16384
#define NTOT 32768       // B * NPIX
#define GRP 64

// ---------------- GEMM tiling ----------------
#define MT 128
#define NT 128
#define KC 32
#define NSTAGE 3
#define NCHUNK (KTOT / KC)         // 36
#define LDP 36                     // padded row length (floats)
#define TILE_FLOATS (128 * LDP)    // per operand per stage
#define STAGE_FLOATS (2 * TILE_FLOATS)
#define SMEM_FLOATS (NSTAGE * STAGE_FLOATS)   // 3*2*4608 = 27648 floats = 110592 B

// ---------------- scratch (__device__ globals; no allocs) ----------------
__device__ float g_offset[(size_t)2 * CO_OFF * NPIX];
__device__ float g_mask  [(size_t)2 * CO_MSK * NPIX];
__device__ float g_cols  [(size_t)NTOT * KTOT];
__device__ float g_wT    [(size_t)MPAD * KTOT];

// ---------------- helpers ----------------
__device__ __forceinline__ uint32_t smem_u32(const void* p) {
    uint32_t a;
    asm("{ .reg .u64 t; cvta.to.shared.u64 t, %1; cvt.u32.u64 %0, t; }" : "=r"(a) : "l"(p));
    return a;
}
__device__ __forceinline__ float to_tf32(float f) {
    float r;
    asm("cvt.rna.tf32.f32 %0, %1;" : "=f"(r) : "f"(f));
    return r;
}
__device__ __forceinline__ void cpasync16(uint32_t dst, const void* src) {
    asm volatile("cp.async.cg.shared.global [%0], [%1], 16;" :: "r"(dst), "l"(src));
}
__device__ __forceinline__ void mma_tf32_16x8x8(float* d, const uint32_t* a, const uint32_t* b) {
    asm volatile(
        "mma.sync.aligned.m16n8k8.row.col.f32.tf32.tf32.f32 "
        "{%0,%1,%2,%3}, {%4,%5,%6,%7}, {%8,%9}, {%0,%1,%2,%3};"
        : "+f"(d[0]), "+f"(d[1]), "+f"(d[2]), "+f"(d[3])
        : "r"(a[0]), "r"(a[1]), "r"(a[2]), "r"(a[3]), "r"(b[0]), "r"(b[1]));
}

// ---------------- stage weights into padded tf32 matrix ----------------
__global__ __launch_bounds__(256) void wstage_kernel(const float* __restrict__ w_off,
                                                     const float* __restrict__ w_msk) {
    size_t idx = (size_t)blockIdx.x * 256 + threadIdx.x;
    if (idx >= (size_t)MPAD * KTOT) return;
    int row = (int)(idx / KTOT);
    int k   = (int)(idx % KTOT);
    float v = 0.f;
    if (row < CO_OFF)      v = w_off[(size_t)row * KTOT + k];
    else if (row < CO_TOT) v = w_msk[(size_t)(row - CO_OFF) * KTOT + k];
    g_wT[idx] = to_tf32(v);
}

// ---------------- im2col (stride 2, pad 1), tf32-rounded ----------------
__global__ __launch_bounds__(128) void im2col_kernel(const float* __restrict__ x) {
    const int ho  = blockIdx.x;
    const int cin = blockIdx.y;
    const int b   = blockIdx.z;
    const int wo  = threadIdx.x;

    const float* xc = x + ((size_t)(b * CIN + cin) << 16);
    float* dst = g_cols + ((size_t)(b * NPIX + ho * WOUT + wo)) * KTOT + cin * 9;

    const int hi0 = 2 * ho - 1;
    const int wi0 = 2 * wo - 1;
#pragma unroll
    for (int ki = 0; ki < 3; ki++) {
        const int hi = hi0 + ki;
        const bool hv = (unsigned)hi < HIN;
#pragma unroll
        for (int kj = 0; kj < 3; kj++) {
            const int wi = wi0 + kj;
            float v = 0.f;
            if (hv && (unsigned)wi < WIN) v = __ldg(xc + (hi << 8) + wi);
            dst[ki * 3 + kj] = to_tf32(v);
        }
    }
}

// ---------------- tf32 mma.sync GEMM + fused bias/sigmoid epilogue ----------------
// D[MPAD, NTOT] = g_wT[MPAD, KTOT] * g_cols[NTOT, KTOT]^T
// CTA: 128x128, 8 warps as 2(m) x 4(n), warp tile 64x32.
__global__ __launch_bounds__(256, 1) void gemm_kernel(const float* __restrict__ b_off,
                                                      const float* __restrict__ b_msk) {
    extern __shared__ float smem[];
    const int tid = threadIdx.x, wid = tid >> 5, lane = tid & 31;
    const int gid = lane >> 2;        // 0..7
    const int tig = lane & 3;         // 0..3
    const int warp_m = wid & 1;       // 0..1 (64 rows each)
    const int warp_n = wid >> 1;      // 0..3 (32 cols each)
    const int m0 = blockIdx.x * MT;
    const int n0 = blockIdx.y * NT;

    const char* abase = (const char*)(g_wT   + (size_t)m0 * KTOT);
    const char* bbase = (const char*)(g_cols + (size_t)n0 * KTOT);

    // stage fill: each operand = 128 rows x 8 granules(16B)
#define FILL(j)                                                                     \
    do {                                                                            \
        float* st = smem + ((j) % NSTAGE) * STAGE_FLOATS;                           \
        uint32_t sa = smem_u32(st);                                                 \
        uint32_t sbp = smem_u32(st + TILE_FLOATS);                                  \
        const char* asrc = abase + (size_t)(j) * (KC * 4);                          \
        const char* bsrc = bbase + (size_t)(j) * (KC * 4);                          \
        for (int g = tid; g < 1024; g += 256) {                                     \
            int r = g >> 3, c = g & 7;                                              \
            cpasync16(sa  + (r * LDP + c * 4) * 4, asrc + (size_t)r * (KTOT * 4) + c * 16); \
            cpasync16(sbp + (r * LDP + c * 4) * 4, bsrc + (size_t)r * (KTOT * 4) + c * 16); \
        }                                                                           \
    } while (0)

    float d[4][4][4];
#pragma unroll
    for (int i = 0; i < 4; i++)
#pragma unroll
        for (int j = 0; j < 4; j++)
#pragma unroll
            for (int c = 0; c < 4; c++) d[i][j][c] = 0.f;

    FILL(0); asm volatile("cp.async.commit_group;" ::: "memory");
    FILL(1); asm volatile("cp.async.commit_group;" ::: "memory");

    for (int i = 0; i < NCHUNK; i++) {
        asm volatile("cp.async.wait_group 1;" ::: "memory");
        __syncthreads();

        if (i + 2 < NCHUNK) { FILL(i + 2); }
        asm volatile("cp.async.commit_group;" ::: "memory");

        const float* As = smem + (i % NSTAGE) * STAGE_FLOATS;
        const float* Bs = As + TILE_FLOATS;
        const float* Aw = As + (warp_m * 64) * LDP;
        const float* Bw = Bs + (warp_n * 32) * LDP;

#pragma unroll
        for (int kk = 0; kk < KC; kk += 8) {
            uint32_t a[4][4], b[4][2];
#pragma unroll
            for (int mt = 0; mt < 4; mt++) {
                const float* ap = Aw + (mt * 16 + gid) * LDP + kk + tig;
                a[mt][0] = __float_as_uint(ap[0]);
                a[mt][1] = __float_as_uint(ap[8 * LDP]);
                a[mt][2] = __float_as_uint(ap[4]);
                a[mt][3] = __float_as_uint(ap[8 * LDP + 4]);
            }
#pragma unroll
            for (int nt = 0; nt < 4; nt++) {
                const float* bp = Bw + (nt * 8 + gid) * LDP + kk + tig;
                b[nt][0] = __float_as_uint(bp[0]);
                b[nt][1] = __float_as_uint(bp[4]);
            }
#pragma unroll
            for (int mt = 0; mt < 4; mt++)
#pragma unroll
                for (int nt = 0; nt < 4; nt++)
                    mma_tf32_16x8x8(d[mt][nt], a[mt], b[nt]);
        }
        __syncthreads();
    }

    // ---- epilogue: bias (+ sigmoid on mask rows), scatter ----
    const int bidx = n0 >> 14;             // batch
    const int pix0 = n0 & (NPIX - 1);

#pragma unroll
    for (int mt = 0; mt < 4; mt++) {
        const int row_lo = m0 + warp_m * 64 + mt * 16 + gid;
#pragma unroll
        for (int half = 0; half < 2; half++) {
            const int row = row_lo + half * 8;
            if (row >= CO_TOT) continue;
            const bool ism = (row >= CO_OFF);
            float bias;
            float* dst;
            if (ism) {
                bias = __ldg(b_msk + (row - CO_OFF));
                dst = g_mask + (size_t)(bidx * CO_MSK + row - CO_OFF) * NPIX + pix0;
            } else {
                bias = __ldg(b_off + row);
                dst = g_offset + (size_t)(bidx * CO_OFF + row) * NPIX + pix0;
            }
#pragma unroll
            for (int nt = 0; nt < 4; nt++) {
                const int col = warp_n * 32 + nt * 8 + tig * 2;
                float v0 = d[mt][nt][half * 2 + 0] + bias;
                float v1 = d[mt][nt][half * 2 + 1] + bias;
                if (ism) {
                    v0 = 1.f / (1.f + __expf(-v0));
                    v1 = 1.f / (1.f + __expf(-v1));
                }
                *(float2*)(dst + col) = make_float2(v0, v1);
            }
        }
    }
}

// ---------------- deformable sampling core ----------------
__global__ __launch_bounds__(128) void deform_kernel(
    const float* __restrict__ x,
    const float* __restrict__ w_deform,
    float* __restrict__ out)
{
    __shared__ float wsh[36];
    const int b = blockIdx.z;
    const int g = blockIdx.y;
    const int pix = blockIdx.x * 128 + threadIdx.x;

    if (threadIdx.x < 36)
        wsh[threadIdx.x] = w_deform[g * 36 + threadIdx.x];
    __syncthreads();

    const int ho = pix >> 7;
    const int wo = pix & 127;

    const float* offp = g_offset + ((size_t)(b * GRP + g) * 18) * NPIX + pix;
    const float* mp   = g_mask   + ((size_t)(b * GRP + g) * 9)  * NPIX + pix;
    const float* xc0  = x + (size_t)(b * CIN + g * 2) * (HIN * WIN);
    const float* xc1  = xc0 + HIN * WIN;

    float acc0 = 0.f, acc1 = 0.f;

#pragma unroll
    for (int k = 0; k < 9; k++) {
        const float dy = offp[(2 * k)     * NPIX];
        const float dx = offp[(2 * k + 1) * NPIX];
        const float m  = mp[k * NPIX];

        const float py = dy + (float)(2 * ho - 1 + k / 3);
        const float px = dx + (float)(2 * wo - 1 + k % 3);
        const float yf = floorf(py);
        const float xf = floorf(px);
        const int y0 = (int)yf;
        const int x0 = (int)xf;
        const float wy = py - yf;
        const float wx = px - xf;

        float v0 = 0.f, v1 = 0.f;
#pragma unroll
        for (int c2 = 0; c2 < 4; c2++) {
            const int yy = y0 + (c2 >> 1);
            const int xx = x0 + (c2 & 1);
            const float wt = ((c2 >> 1) ? wy : (1.f - wy)) *
                             ((c2 & 1)  ? wx : (1.f - wx));
            if (yy >= 0 && yy < HIN && xx >= 0 && xx < WIN) {
                const int idx = yy * WIN + xx;
                v0 += wt * __ldg(xc0 + idx);
                v1 += wt * __ldg(xc1 + idx);
            }
        }
        v0 *= m;
        v1 *= m;
        acc0 += wsh[k]      * v0 + wsh[9 + k]  * v1;
        acc1 += wsh[18 + k] * v0 + wsh[27 + k] * v1;
    }

    out[((size_t)(b * CIN + g * 2))     * NPIX + pix] = acc0;
    out[((size_t)(b * CIN + g * 2) + 1) * NPIX + pix] = acc1;
}

// ---------------- launch ----------------
extern "C" void kernel_launch(void* const* d_in, const int* in_sizes, int n_in,
                              void* d_out, int out_size)
{
    const float* x        = (const float*)d_in[0];
    const float* w_offset = (const float*)d_in[1];
    const float* b_offset = (const float*)d_in[2];
    const float* w_mask   = (const float*)d_in[3];
    const float* b_mask   = (const float*)d_in[4];
    const float* w_deform = (const float*)d_in[5];
    float* out = (float*)d_out;

    wstage_kernel<<<(MPAD * KTOT + 255) / 256, 256>>>(w_offset, w_mask);
    im2col_kernel<<<dim3(HOUT, CIN, 2), 128>>>(x);

    cudaFuncSetAttribute(gemm_kernel, cudaFuncAttributeMaxDynamicSharedMemorySize,
                         SMEM_FLOATS * 4);
    gemm_kernel<<<dim3(MPAD / MT, NTOT / NT), 256, SMEM_FLOATS * 4>>>(b_offset, b_mask);

    deform_kernel<<<dim3(NPIX / 128, GRP, 2), 128>>>(x, w_deform, out);
}

// round 6
// speedup vs baseline: 5.8019x; 1.6394x over previous
#include <cuda_runtime.h>
#include <cuda_fp16.h>
#include <cstdint>
#include <math.h>

// ---------------- problem constants ----------------
#define HIN 256
#define WIN 256
#define HOUT 128
#define WOUT 128
#define CIN 128
#define CO_OFF 1152      // G*2*K
#define CO_MSK 576       // G*K
#define CO_TOT 1728
#define MPAD 1792        // 14 * 128
#define KTOT 1152        // CIN * 9
#define NPIX 16384
#define NTOT 32768       // B * NPIX
#define GRP 64

// ---------------- GEMM tiling ----------------
#define MT 128
#define NT 128
#define KC 64                       // K per pipeline chunk
#define NSTAGE 3
#define NCHUNK (KTOT / KC)          // 18
#define LDPh 72                     // padded row length in halves (144 B, 16B-mult)
#define TILE_HALVES (128 * LDPh)    // per operand per stage
#define STAGE_HALVES (2 * TILE_HALVES)
#define SMEM_BYTES (NSTAGE * STAGE_HALVES * 2)   // 3*2*9216*2 = 110592 B

// ---------------- scratch (__device__ globals; no allocs) ----------------
__device__ float  g_offset[(size_t)2 * CO_OFF * NPIX];
__device__ float  g_mask  [(size_t)2 * CO_MSK * NPIX];
__device__ __half g_colsh [(size_t)NTOT * KTOT];
__device__ __half g_wTh   [(size_t)MPAD * KTOT];

// ---------------- helpers ----------------
__device__ __forceinline__ uint32_t smem_u32(const void* p) {
    uint32_t a;
    asm("{ .reg .u64 t; cvta.to.shared.u64 t, %1; cvt.u32.u64 %0, t; }" : "=r"(a) : "l"(p));
    return a;
}
__device__ __forceinline__ void cpasync16(uint32_t dst, const void* src) {
    asm volatile("cp.async.cg.shared.global [%0], [%1], 16;" :: "r"(dst), "l"(src));
}
__device__ __forceinline__ void mma_f16_16x8x16(float* d, const uint32_t* a, const uint32_t* b) {
    asm volatile(
        "mma.sync.aligned.m16n8k16.row.col.f32.f16.f16.f32 "
        "{%0,%1,%2,%3}, {%4,%5,%6,%7}, {%8,%9}, {%0,%1,%2,%3};"
        : "+f"(d[0]), "+f"(d[1]), "+f"(d[2]), "+f"(d[3])
        : "r"(a[0]), "r"(a[1]), "r"(a[2]), "r"(a[3]), "r"(b[0]), "r"(b[1]));
}

// ---------------- stage weights into padded fp16 matrix ----------------
__global__ __launch_bounds__(256) void wstage_kernel(const float* __restrict__ w_off,
                                                     const float* __restrict__ w_msk) {
    size_t idx = (size_t)blockIdx.x * 256 + threadIdx.x;
    if (idx >= (size_t)MPAD * KTOT) return;
    int row = (int)(idx / KTOT);
    int k   = (int)(idx % KTOT);
    float v = 0.f;
    if (row < CO_OFF)      v = w_off[(size_t)row * KTOT + k];
    else if (row < CO_TOT) v = w_msk[(size_t)(row - CO_OFF) * KTOT + k];
    g_wTh[idx] = __float2half_rn(v);
}

// ---------------- im2col (stride 2, pad 1) -> fp16 ----------------
__global__ __launch_bounds__(128) void im2col_kernel(const float* __restrict__ x) {
    const int ho  = blockIdx.x;
    const int cin = blockIdx.y;
    const int b   = blockIdx.z;
    const int wo  = threadIdx.x;

    const float* xc = x + ((size_t)(b * CIN + cin) << 16);
    __half* dst = g_colsh + ((size_t)(b * NPIX + ho * WOUT + wo)) * KTOT + cin * 9;

    const int hi0 = 2 * ho - 1;
    const int wi0 = 2 * wo - 1;
#pragma unroll
    for (int ki = 0; ki < 3; ki++) {
        const int hi = hi0 + ki;
        const bool hv = (unsigned)hi < HIN;
#pragma unroll
        for (int kj = 0; kj < 3; kj++) {
            const int wi = wi0 + kj;
            float v = 0.f;
            if (hv && (unsigned)wi < WIN) v = __ldg(xc + (hi << 8) + wi);
            dst[ki * 3 + kj] = __float2half_rn(v);
        }
    }
}

// ---------------- fp16 mma.sync GEMM + fused bias/sigmoid epilogue ----------------
// D[MPAD, NTOT] = g_wTh[MPAD, KTOT] * g_colsh[NTOT, KTOT]^T
// CTA: 128x128, 8 warps as 2(m) x 4(n), warp tile 64x32.
__global__ __launch_bounds__(256, 2) void gemm_kernel(const float* __restrict__ b_off,
                                                      const float* __restrict__ b_msk) {
    extern __shared__ __half smem[];
    const int tid = threadIdx.x, wid = tid >> 5, lane = tid & 31;
    const int gid = lane >> 2;        // 0..7
    const int tig = lane & 3;         // 0..3
    const int warp_m = wid & 1;       // 0..1 (64 rows each)
    const int warp_n = wid >> 1;      // 0..3 (32 cols each)
    const int m0 = blockIdx.x * MT;
    const int n0 = blockIdx.y * NT;

    const char* abase = (const char*)(g_wTh   + (size_t)m0 * KTOT);
    const char* bbase = (const char*)(g_colsh + (size_t)n0 * KTOT);

    // stage fill: each operand = 128 rows x 8 granules(16B = 8 halves)
#define FILL(j)                                                                      \
    do {                                                                             \
        __half* st = smem + ((j) % NSTAGE) * STAGE_HALVES;                           \
        uint32_t sa  = smem_u32(st);                                                 \
        uint32_t sbp = smem_u32(st + TILE_HALVES);                                   \
        const char* asrc = abase + (size_t)(j) * (KC * 2);                           \
        const char* bsrc = bbase + (size_t)(j) * (KC * 2);                           \
        for (int g = tid; g < 1024; g += 256) {                                      \
            int r = g >> 3, c = g & 7;                                               \
            cpasync16(sa  + (r * LDPh + c * 8) * 2, asrc + (size_t)r * (KTOT * 2) + c * 16); \
            cpasync16(sbp + (r * LDPh + c * 8) * 2, bsrc + (size_t)r * (KTOT * 2) + c * 16); \
        }                                                                            \
    } while (0)

    float d[4][4][4];
#pragma unroll
    for (int i = 0; i < 4; i++)
#pragma unroll
        for (int j = 0; j < 4; j++)
#pragma unroll
            for (int c = 0; c < 4; c++) d[i][j][c] = 0.f;

    FILL(0); asm volatile("cp.async.commit_group;" ::: "memory");
    FILL(1); asm volatile("cp.async.commit_group;" ::: "memory");

    for (int i = 0; i < NCHUNK; i++) {
        asm volatile("cp.async.wait_group 1;" ::: "memory");
        __syncthreads();

        if (i + 2 < NCHUNK) { FILL(i + 2); }
        asm volatile("cp.async.commit_group;" ::: "memory");

        const __half* As = smem + (i % NSTAGE) * STAGE_HALVES;
        const __half* Bs = As + TILE_HALVES;
        const __half* Aw = As + (warp_m * 64) * LDPh;
        const __half* Bw = Bs + (warp_n * 32) * LDPh;

#pragma unroll
        for (int kk = 0; kk < KC; kk += 16) {
            uint32_t a[4][4], b[4][2];
#pragma unroll
            for (int mt = 0; mt < 4; mt++) {
                const __half* ap = Aw + (mt * 16 + gid) * LDPh + kk + 2 * tig;
                a[mt][0] = *(const uint32_t*)(ap);
                a[mt][1] = *(const uint32_t*)(ap + 8 * LDPh);
                a[mt][2] = *(const uint32_t*)(ap + 8);
                a[mt][3] = *(const uint32_t*)(ap + 8 * LDPh + 8);
            }
#pragma unroll
            for (int nt = 0; nt < 4; nt++) {
                const __half* bp = Bw + (nt * 8 + gid) * LDPh + kk + 2 * tig;
                b[nt][0] = *(const uint32_t*)(bp);
                b[nt][1] = *(const uint32_t*)(bp + 8);
            }
#pragma unroll
            for (int mt = 0; mt < 4; mt++)
#pragma unroll
                for (int nt = 0; nt < 4; nt++)
                    mma_f16_16x8x16(d[mt][nt], a[mt], b[nt]);
        }
        __syncthreads();
    }

    // ---- epilogue: bias (+ sigmoid on mask rows), scatter ----
    const int bidx = n0 >> 14;             // batch
    const int pix0 = n0 & (NPIX - 1);

#pragma unroll
    for (int mt = 0; mt < 4; mt++) {
        const int row_lo = m0 + warp_m * 64 + mt * 16 + gid;
#pragma unroll
        for (int half = 0; half < 2; half++) {
            const int row = row_lo + half * 8;
            if (row >= CO_TOT) continue;
            const bool ism = (row >= CO_OFF);
            float bias;
            float* dst;
            if (ism) {
                bias = __ldg(b_msk + (row - CO_OFF));
                dst = g_mask + (size_t)(bidx * CO_MSK + row - CO_OFF) * NPIX + pix0;
            } else {
                bias = __ldg(b_off + row);
                dst = g_offset + (size_t)(bidx * CO_OFF + row) * NPIX + pix0;
            }
#pragma unroll
            for (int nt = 0; nt < 4; nt++) {
                const int col = warp_n * 32 + nt * 8 + tig * 2;
                float v0 = d[mt][nt][half * 2 + 0] + bias;
                float v1 = d[mt][nt][half * 2 + 1] + bias;
                if (ism) {
                    v0 = 1.f / (1.f + __expf(-v0));
                    v1 = 1.f / (1.f + __expf(-v1));
                }
                *(float2*)(dst + col) = make_float2(v0, v1);
            }
        }
    }
}

// ---------------- deformable sampling core ----------------
__global__ __launch_bounds__(128) void deform_kernel(
    const float* __restrict__ x,
    const float* __restrict__ w_deform,
    float* __restrict__ out)
{
    __shared__ float wsh[36];
    const int b = blockIdx.z;
    const int g = blockIdx.y;
    const int pix = blockIdx.x * 128 + threadIdx.x;

    if (threadIdx.x < 36)
        wsh[threadIdx.x] = w_deform[g * 36 + threadIdx.x];
    __syncthreads();

    const int ho = pix >> 7;
    const int wo = pix & 127;

    const float* offp = g_offset + ((size_t)(b * GRP + g) * 18) * NPIX + pix;
    const float* mp   = g_mask   + ((size_t)(b * GRP + g) * 9)  * NPIX + pix;
    const float* xc0  = x + (size_t)(b * CIN + g * 2) * (HIN * WIN);
    const float* xc1  = xc0 + HIN * WIN;

    float acc0 = 0.f, acc1 = 0.f;

#pragma unroll
    for (int k = 0; k < 9; k++) {
        const float dy = offp[(2 * k)     * NPIX];
        const float dx = offp[(2 * k + 1) * NPIX];
        const float m  = mp[k * NPIX];

        const float py = dy + (float)(2 * ho - 1 + k / 3);
        const float px = dx + (float)(2 * wo - 1 + k % 3);
        const float yf = floorf(py);
        const float xf = floorf(px);
        const int y0 = (int)yf;
        const int x0 = (int)xf;
        const float wy = py - yf;
        const float wx = px - xf;

        float v0 = 0.f, v1 = 0.f;
#pragma unroll
        for (int c2 = 0; c2 < 4; c2++) {
            const int yy = y0 + (c2 >> 1);
            const int xx = x0 + (c2 & 1);
            const float wt = ((c2 >> 1) ? wy : (1.f - wy)) *
                             ((c2 & 1)  ? wx : (1.f - wx));
            if (yy >= 0 && yy < HIN && xx >= 0 && xx < WIN) {
                const int idx = yy * WIN + xx;
                v0 += wt * __ldg(xc0 + idx);
                v1 += wt * __ldg(xc1 + idx);
            }
        }
        v0 *= m;
        v1 *= m;
        acc0 += wsh[k]      * v0 + wsh[9 + k]  * v1;
        acc1 += wsh[18 + k] * v0 + wsh[27 + k] * v1;
    }

    out[((size_t)(b * CIN + g * 2))     * NPIX + pix] = acc0;
    out[((size_t)(b * CIN + g * 2) + 1) * NPIX + pix] = acc1;
}

// ---------------- launch ----------------
extern "C" void kernel_launch(void* const* d_in, const int* in_sizes, int n_in,
                              void* d_out, int out_size)
{
    const float* x        = (const float*)d_in[0];
    const float* w_offset = (const float*)d_in[1];
    const float* b_offset = (const float*)d_in[2];
    const float* w_mask   = (const float*)d_in[3];
    const float* b_mask   = (const float*)d_in[4];
    const float* w_deform = (const float*)d_in[5];
    float* out = (float*)d_out;

    wstage_kernel<<<(MPAD * KTOT + 255) / 256, 256>>>(w_offset, w_mask);
    im2col_kernel<<<dim3(HOUT, CIN, 2), 128>>>(x);

    cudaFuncSetAttribute(gemm_kernel, cudaFuncAttributeMaxDynamicSharedMemorySize,
                         SMEM_BYTES);
    gemm_kernel<<<dim3(MPAD / MT, NTOT / NT), 256, SMEM_BYTES>>>(b_offset, b_mask);

    deform_kernel<<<dim3(NPIX / 128, GRP, 2), 128>>>(x, w_deform, out);
}

// round 7
// speedup vs baseline: 9.1235x; 1.5725x over previous
#include <cuda_runtime.h>
#include <cuda_fp16.h>
#include <cstdint>
#include <math.h>

// ---------------- problem constants ----------------
#define HIN 256
#define WIN 256
#define HOUT 128
#define WOUT 128
#define CIN 128
#define CO_OFF 1152      // G*2*K
#define CO_MSK 576       // G*K
#define CO_TOT 1728
#define MPAD 1792        // 14 * 128
#define KTOT 1152        // CIN * 9
#define NPIX 16384
#define NTOT 32768       // B * NPIX
#define GRP 64

// ---------------- GEMM tiling ----------------
#define MT 128
#define NT 128
#define KC 64                       // K per pipeline chunk
#define NSTAGE 3
#define NCHUNK (KTOT / KC)          // 18
#define LDPh 72                     // padded row length in halves (144 B)
#define TILE_HALVES (128 * LDPh)
#define STAGE_HALVES (2 * TILE_HALVES)
#define SMEM_BYTES (NSTAGE * STAGE_HALVES * 2)   // 110592 B

// im2col staging
#define I2C_PIX 16
#define I2C_PAD 1192                 // padded row stride in halves (2384 B, 16B mult)

// ---------------- scratch (__device__ globals; no allocs) ----------------
__device__ float  g_offset[(size_t)2 * CO_OFF * NPIX];
__device__ float  g_mask  [(size_t)2 * CO_MSK * NPIX];
__device__ __half g_colsh [(size_t)NTOT * KTOT];
__device__ __half g_wTh   [(size_t)MPAD * KTOT];

// ---------------- helpers ----------------
__device__ __forceinline__ uint32_t smem_u32(const void* p) {
    uint32_t a;
    asm("{ .reg .u64 t; cvta.to.shared.u64 t, %1; cvt.u32.u64 %0, t; }" : "=r"(a) : "l"(p));
    return a;
}
__device__ __forceinline__ void cpasync16(uint32_t dst, const void* src) {
    asm volatile("cp.async.cg.shared.global [%0], [%1], 16;" :: "r"(dst), "l"(src));
}
__device__ __forceinline__ void ldmx4(uint32_t* r, uint32_t addr) {
    asm volatile("ldmatrix.sync.aligned.m8n8.x4.shared.b16 {%0,%1,%2,%3}, [%4];"
                 : "=r"(r[0]), "=r"(r[1]), "=r"(r[2]), "=r"(r[3]) : "r"(addr));
}
__device__ __forceinline__ void mma_f16_16x8x16(float* d, const uint32_t* a, const uint32_t* b) {
    asm volatile(
        "mma.sync.aligned.m16n8k16.row.col.f32.f16.f16.f32 "
        "{%0,%1,%2,%3}, {%4,%5,%6,%7}, {%8,%9}, {%0,%1,%2,%3};"
        : "+f"(d[0]), "+f"(d[1]), "+f"(d[2]), "+f"(d[3])
        : "r"(a[0]), "r"(a[1]), "r"(a[2]), "r"(a[3]), "r"(b[0]), "r"(b[1]));
}

// ---------------- stage weights into padded fp16 matrix ----------------
__global__ __launch_bounds__(256) void wstage_kernel(const float* __restrict__ w_off,
                                                     const float* __restrict__ w_msk) {
    size_t idx = (size_t)blockIdx.x * 256 + threadIdx.x;
    if (idx >= (size_t)MPAD * KTOT) return;
    int row = (int)(idx / KTOT);
    int k   = (int)(idx % KTOT);
    float v = 0.f;
    if (row < CO_OFF)      v = w_off[(size_t)row * KTOT + k];
    else if (row < CO_TOT) v = w_msk[(size_t)(row - CO_OFF) * KTOT + k];
    g_wTh[idx] = __float2half_rn(v);
}

// ---------------- im2col v2: smem-staged, coalesced 16B output ----------------
// block: 256 thr, handles 16 pixels (one ho, 16 consecutive wo) x all 128 cins.
__global__ __launch_bounds__(256) void im2col_kernel(const float* __restrict__ x) {
    __shared__ __half buf[I2C_PIX * I2C_PAD];   // ~38 KB

    const int p0 = blockIdx.x * I2C_PIX;
    const int ho = blockIdx.y;
    const int b  = blockIdx.z;
    const int tid = threadIdx.x;
    const int px   = tid & 15;     // pixel in tile
    const int csub = tid >> 4;     // 0..15 cin sub-index

    const int wo  = p0 + px;
    const int hi0 = 2 * ho - 1;
    const int wi0 = 2 * wo - 1;

    // phase 1: gather into padded smem rows [px][k]
    for (int cb = 0; cb < CIN; cb += 16) {
        const int cin = cb + csub;
        const float* xc = x + ((size_t)(b * CIN + cin) << 16);
        __half* dst = buf + px * I2C_PAD + cin * 9;
#pragma unroll
        for (int ki = 0; ki < 3; ki++) {
            const int hi = hi0 + ki;
            const bool hv = (unsigned)hi < HIN;
#pragma unroll
            for (int kj = 0; kj < 3; kj++) {
                const int wi = wi0 + kj;
                float v = 0.f;
                if (hv && (unsigned)wi < WIN) v = __ldg(xc + (hi << 8) + wi);
                dst[ki * 3 + kj] = __float2half_rn(v);
            }
        }
    }
    __syncthreads();

    // phase 2: stream out 16 rows x 2304 B, fully coalesced
    int4* gdst = (int4*)(g_colsh + ((size_t)(b * NPIX + ho * WOUT + p0)) * KTOT);
    const int NG = I2C_PIX * (KTOT / 8);  // 2304 granules
    for (int i = tid; i < NG; i += 256) {
        const int p = i / (KTOT / 8);
        const int g = i - p * (KTOT / 8);
        gdst[(size_t)p * (KTOT / 8) + g] = ((const int4*)(buf + p * I2C_PAD))[g];
    }
}

// ---------------- fp16 mma.sync GEMM (ldmatrix) + fused epilogue ----------------
// D[MPAD, NTOT] = g_wTh[MPAD, KTOT] * g_colsh[NTOT, KTOT]^T
// CTA: 128x128, 8 warps as 2(m) x 4(n), warp tile 64x32.
__global__ __launch_bounds__(256, 2) void gemm_kernel(const float* __restrict__ b_off,
                                                      const float* __restrict__ b_msk) {
    extern __shared__ __half smem[];
    const int tid = threadIdx.x, wid = tid >> 5, lane = tid & 31;
    const int gid = lane >> 2;
    const int tig = lane & 3;
    const int warp_m = wid & 1;
    const int warp_n = wid >> 1;
    const int m0 = blockIdx.x * MT;
    const int n0 = blockIdx.y * NT;

    const char* abase = (const char*)(g_wTh   + (size_t)m0 * KTOT);
    const char* bbase = (const char*)(g_colsh + (size_t)n0 * KTOT);

#define FILL(j)                                                                      \
    do {                                                                             \
        __half* st = smem + ((j) % NSTAGE) * STAGE_HALVES;                           \
        uint32_t sa  = smem_u32(st);                                                 \
        uint32_t sbp = smem_u32(st + TILE_HALVES);                                   \
        const char* asrc = abase + (size_t)(j) * (KC * 2);                           \
        const char* bsrc = bbase + (size_t)(j) * (KC * 2);                           \
        for (int g = tid; g < 1024; g += 256) {                                      \
            int r = g >> 3, c = g & 7;                                               \
            cpasync16(sa  + (r * LDPh + c * 8) * 2, asrc + (size_t)r * (KTOT * 2) + c * 16); \
            cpasync16(sbp + (r * LDPh + c * 8) * 2, bsrc + (size_t)r * (KTOT * 2) + c * 16); \
        }                                                                            \
    } while (0)

    float d[4][4][4];
#pragma unroll
    for (int i = 0; i < 4; i++)
#pragma unroll
        for (int j = 0; j < 4; j++)
#pragma unroll
            for (int c = 0; c < 4; c++) d[i][j][c] = 0.f;

    // ldmatrix per-lane address components (element offsets within the warp tile)
    const int lrow = lane & 15;             // row within 16-row block
    const int lkof = (lane >> 4) << 3;      // 0 or 8 (k half for A)
    // B x4: lanes 0-15 -> n-block 0 (rows lane&7, k half (lane>>3)&1),
    //       lanes 16-31 -> n-block 1
    const int bnrow = lane & 7;
    const int bkof  = ((lane >> 3) & 1) << 3;
    const int bblk  = lane >> 4;            // 0 or 1

    FILL(0); asm volatile("cp.async.commit_group;" ::: "memory");
    FILL(1); asm volatile("cp.async.commit_group;" ::: "memory");

    for (int i = 0; i < NCHUNK; i++) {
        asm volatile("cp.async.wait_group 1;" ::: "memory");
        __syncthreads();

        if (i + 2 < NCHUNK) { FILL(i + 2); }
        asm volatile("cp.async.commit_group;" ::: "memory");

        const __half* As = smem + (i % NSTAGE) * STAGE_HALVES;
        const __half* Bs = As + TILE_HALVES;
        // base smem addrs for this warp's sub-tiles
        const uint32_t aw = smem_u32(As + (warp_m * 64) * LDPh);
        const uint32_t bw = smem_u32(Bs + (warp_n * 32) * LDPh);

#pragma unroll
        for (int kk = 0; kk < KC; kk += 16) {
            uint32_t a[4][4], b2[2][4];
#pragma unroll
            for (int mt = 0; mt < 4; mt++) {
                uint32_t addr = aw + ((mt * 16 + lrow) * LDPh + kk + lkof) * 2;
                ldmx4(a[mt], addr);
            }
#pragma unroll
            for (int nb = 0; nb < 2; nb++) {
                // covers nt = 2*nb (lanes 0-15) and nt = 2*nb+1 (lanes 16-31)
                uint32_t addr = bw + (((nb * 2 + bblk) * 8 + bnrow) * LDPh + kk + bkof) * 2;
                ldmx4(b2[nb], addr);
            }
#pragma unroll
            for (int mt = 0; mt < 4; mt++) {
#pragma unroll
                for (int nb = 0; nb < 2; nb++) {
                    mma_f16_16x8x16(d[mt][nb * 2 + 0], a[mt], &b2[nb][0]);
                    mma_f16_16x8x16(d[mt][nb * 2 + 1], a[mt], &b2[nb][2]);
                }
            }
        }
        __syncthreads();
    }

    // ---- epilogue: bias (+ sigmoid on mask rows), scatter ----
    const int bidx = n0 >> 14;
    const int pix0 = n0 & (NPIX - 1);

#pragma unroll
    for (int mt = 0; mt < 4; mt++) {
        const int row_lo = m0 + warp_m * 64 + mt * 16 + gid;
#pragma unroll
        for (int half = 0; half < 2; half++) {
            const int row = row_lo + half * 8;
            if (row >= CO_TOT) continue;
            const bool ism = (row >= CO_OFF);
            float bias;
            float* dst;
            if (ism) {
                bias = __ldg(b_msk + (row - CO_OFF));
                dst = g_mask + (size_t)(bidx * CO_MSK + row - CO_OFF) * NPIX + pix0;
            } else {
                bias = __ldg(b_off + row);
                dst = g_offset + (size_t)(bidx * CO_OFF + row) * NPIX + pix0;
            }
#pragma unroll
            for (int nt = 0; nt < 4; nt++) {
                const int col = warp_n * 32 + nt * 8 + tig * 2;
                float v0 = d[mt][nt][half * 2 + 0] + bias;
                float v1 = d[mt][nt][half * 2 + 1] + bias;
                if (ism) {
                    v0 = 1.f / (1.f + __expf(-v0));
                    v1 = 1.f / (1.f + __expf(-v1));
                }
                *(float2*)(dst + col) = make_float2(v0, v1);
            }
        }
    }
}

// ---------------- deformable sampling core ----------------
__global__ __launch_bounds__(128) void deform_kernel(
    const float* __restrict__ x,
    const float* __restrict__ w_deform,
    float* __restrict__ out)
{
    __shared__ float wsh[36];
    const int b = blockIdx.z;
    const int g = blockIdx.y;
    const int pix = blockIdx.x * 128 + threadIdx.x;

    if (threadIdx.x < 36)
        wsh[threadIdx.x] = w_deform[g * 36 + threadIdx.x];
    __syncthreads();

    const int ho = pix >> 7;
    const int wo = pix & 127;

    const float* offp = g_offset + ((size_t)(b * GRP + g) * 18) * NPIX + pix;
    const float* mp   = g_mask   + ((size_t)(b * GRP + g) * 9)  * NPIX + pix;
    const float* xc0  = x + (size_t)(b * CIN + g * 2) * (HIN * WIN);
    const float* xc1  = xc0 + HIN * WIN;

    float acc0 = 0.f, acc1 = 0.f;

#pragma unroll
    for (int k = 0; k < 9; k++) {
        const float dy = offp[(2 * k)     * NPIX];
        const float dx = offp[(2 * k + 1) * NPIX];
        const float m  = mp[k * NPIX];

        const float py = dy + (float)(2 * ho - 1 + k / 3);
        const float px = dx + (float)(2 * wo - 1 + k % 3);
        const float yf = floorf(py);
        const float xf = floorf(px);
        const int y0 = (int)yf;
        const int x0 = (int)xf;
        const float wy = py - yf;
        const float wx = px - xf;

        float v0 = 0.f, v1 = 0.f;
#pragma unroll
        for (int c2 = 0; c2 < 4; c2++) {
            const int yy = y0 + (c2 >> 1);
            const int xx = x0 + (c2 & 1);
            const float wt = ((c2 >> 1) ? wy : (1.f - wy)) *
                             ((c2 & 1)  ? wx : (1.f - wx));
            if (yy >= 0 && yy < HIN && xx >= 0 && xx < WIN) {
                const int idx = yy * WIN + xx;
                v0 += wt * __ldg(xc0 + idx);
                v1 += wt * __ldg(xc1 + idx);
            }
        }
        v0 *= m;
        v1 *= m;
        acc0 += wsh[k]      * v0 + wsh[9 + k]  * v1;
        acc1 += wsh[18 + k] * v0 + wsh[27 + k] * v1;
    }

    out[((size_t)(b * CIN + g * 2))     * NPIX + pix] = acc0;
    out[((size_t)(b * CIN + g * 2) + 1) * NPIX + pix] = acc1;
}

// ---------------- launch ----------------
extern "C" void kernel_launch(void* const* d_in, const int* in_sizes, int n_in,
                              void* d_out, int out_size)
{
    const float* x        = (const float*)d_in[0];
    const float* w_offset = (const float*)d_in[1];
    const float* b_offset = (const float*)d_in[2];
    const float* w_mask   = (const float*)d_in[3];
    const float* b_mask   = (const float*)d_in[4];
    const float* w_deform = (const float*)d_in[5];
    float* out = (float*)d_out;

    wstage_kernel<<<(MPAD * KTOT + 255) / 256, 256>>>(w_offset, w_mask);
    im2col_kernel<<<dim3(WOUT / I2C_PIX, HOUT, 2), 256>>>(x);

    cudaFuncSetAttribute(gemm_kernel, cudaFuncAttributeMaxDynamicSharedMemorySize,
                         SMEM_BYTES);
    gemm_kernel<<<dim3(MPAD / MT, NTOT / NT), 256, SMEM_BYTES>>>(b_offset, b_mask);

    deform_kernel<<<dim3(NPIX / 128, GRP, 2), 128>>>(x, w_deform, out);
}